// round 4
// baseline (speedup 1.0000x reference)
#include <cuda_runtime.h>

// BicycleModel: B=65536 vehicles, 256 steps, 4 output planes [B,256] f32.
// R4: warp-autonomous (each warp = 32 vehicles, private smem, __syncwarp only),
// state staged as ONE float4 (x,y,yaw,sp) per (v,t) -> STS.128 in compute,
// conflict-free LDS.128 + register 4x4 transpose + coalesced STG.128 in store.

constexpr int BV  = 65536;
constexpr int NS  = 256;
constexpr int BLK = 64;            // 2 independent warps per block
constexpr int TC  = 16;            // timesteps per chunk
constexpr int NCH = NS / TC;       // 16
constexpr int NF4 = NS / 4;        // 64 float4 per row
constexpr int SPAD = TC + 1;       // state row: 17 float4 (odd -> conflict-free)
constexpr int CPAD = TC + 1;       // control row: 17 floats (odd -> conflict-free)

constexpr float DT        = 0.05f;
constexpr float MAX_STEER = 0.52359877559829887f;   // 30 deg
constexpr float MAX_SPEED = 100.0f;
constexpr float INV_WB    = 1.0f / 2.7f;

__global__ __launch_bounds__(BLK)
void bicycle_kernel(const float*  __restrict__ sx,
                    const float*  __restrict__ sy,
                    const float*  __restrict__ syaw,
                    const float*  __restrict__ ssp,
                    const float4* __restrict__ acc,
                    const float4* __restrict__ str,
                    float4*       __restrict__ out)
{
    // Per-warp regions: state 32*17 float4 (8704B) + 2 control arrays 32*17 f32
    // (2176B each) = 13056B/warp -> 26112B/block -> 8 blocks/SM.
    __shared__ float4 st_s[2][32 * SPAD];
    __shared__ float  ac_s[2][32 * CPAD];
    __shared__ float  sr_s[2][32 * CPAD];

    const int tid  = threadIdx.x;
    const int lane = tid & 31;
    const int wrp  = tid >> 5;

    float4* s_st  = st_s[wrp];
    float*  s_acc = ac_s[wrp];
    float*  s_str = sr_s[wrp];

    const int vbase = blockIdx.x * BLK + wrp * 32;   // this warp's vehicle base
    const int b     = vbase + lane;

    float x   = sx[b];
    float y   = sy[b];
    float yaw = syaw[b];
    float sp  = ssp[b];

    const unsigned plane4 = (unsigned)BV * NF4;
    const float4* arow = acc + (unsigned)vbase * NF4;
    const float4* srow = str + (unsigned)vbase * NF4;
    float4* ox = out + (unsigned)vbase * NF4;

    float*  pa = s_acc + lane * CPAD;
    float*  ps = s_str + lane * CPAD;
    float4* qs = s_st  + lane * SPAD;

    float4 ra[4], rs[4];

    // ---- Prologue: load + stage controls for chunk 0 ----
    // f4 = it*32 + lane -> (v = f4>>2, t4 = f4&3): warp covers 8 vehicles x 64B
    // contiguous segments per instruction (8 wavefronts, ideal for this layout).
#pragma unroll
    for (int it = 0; it < 4; ++it) {
        int f4 = it * 32 + lane;
        int v  = f4 >> 2, t4 = f4 & 3;
        float4 a4 = arow[(unsigned)v * NF4 + t4];
        float4 s4 = srow[(unsigned)v * NF4 + t4];
        int o = v * CPAD + t4 * 4;
        s_acc[o] = a4.x; s_acc[o+1] = a4.y; s_acc[o+2] = a4.z; s_acc[o+3] = a4.w;
        s_str[o] = s4.x; s_str[o+1] = s4.y; s_str[o+2] = s4.z; s_str[o+3] = s4.w;
    }
    __syncwarp();

    for (int c = 0; c < NCH; ++c) {
        // ---- Prefetch controls for chunk c+1 into registers ----
        if (c + 1 < NCH) {
#pragma unroll
            for (int it = 0; it < 4; ++it) {
                int f4 = it * 32 + lane;
                int v  = f4 >> 2, t4 = f4 & 3;
                unsigned g4 = (unsigned)v * NF4 + (unsigned)(c + 1) * 4 + t4;
                ra[it] = arow[g4];
                rs[it] = srow[g4];
            }
        }

        // ---- Compute 16 steps; stage pre-step state as float4 (STS.128) ----
        // STS addr (float4 units): lane*17 + j -> 17*lane mod 8 = lane mod 8,
        // distinct within each 8-lane crossbar phase: conflict-free.
#pragma unroll
        for (int j = 0; j < TC; ++j) {
            qs[j] = make_float4(x, y, yaw, sp);

            float A  = pa[j];
            float ST = ps[j];

            float fr   = fmaf(0.01f * sp, sp, 0.1f * sp);
            float spn  = fminf(fmaxf(fmaf(DT, A - fr, sp), 0.0f), MAX_SPEED);
            float sc   = fminf(fmaxf(ST, -MAX_STEER), MAX_STEER);
            float angv = sp * __tanf(sc) * INV_WB;
            float sn, cs;
            __sincosf(yaw, &sn, &cs);
            x   = fmaf(sp * cs, DT, x);
            y   = fmaf(sp * sn, DT, y);
            yaw = fmaf(angv, DT, yaw);
            sp  = spn;
        }
        __syncwarp();

        // ---- Store: gather 4 state float4s, 4x4 transpose, 4x STG.128 ----
        // lane -> (v = it*8 + (lane&7), t4 = lane>>3): LDS.128 at v*17 + t4*4 + k
        // is conflict-free (8 distinct v per phase, 17v mod 8 = v).
#pragma unroll
        for (int it = 0; it < 4; ++it) {
            int v  = it * 8 + (lane & 7);
            int t4 = lane >> 3;
            const float4* src = s_st + v * SPAD + t4 * 4;
            float4 s0 = src[0], s1 = src[1], s2 = src[2], s3 = src[3];

            unsigned g4 = (unsigned)v * NF4 + (unsigned)c * 4 + t4;
            ox[g4]              = make_float4(s0.x, s1.x, s2.x, s3.x);  // x
            ox[plane4 + g4]     = make_float4(s0.y, s1.y, s2.y, s3.y);  // y
            ox[2*plane4 + g4]   = make_float4(s0.z, s1.z, s2.z, s3.z);  // yaw
            ox[3*plane4 + g4]   = make_float4(s0.w, s1.w, s2.w, s3.w);  // speed
        }

        // ---- Stage prefetched controls for next chunk ----
        if (c + 1 < NCH) {
#pragma unroll
            for (int it = 0; it < 4; ++it) {
                int f4 = it * 32 + lane;
                int v  = f4 >> 2, t4 = f4 & 3;
                int o  = v * CPAD + t4 * 4;
                s_acc[o] = ra[it].x; s_acc[o+1] = ra[it].y; s_acc[o+2] = ra[it].z; s_acc[o+3] = ra[it].w;
                s_str[o] = rs[it].x; s_str[o+1] = rs[it].y; s_str[o+2] = rs[it].z; s_str[o+3] = rs[it].w;
            }
        }
        __syncwarp();
    }
}

extern "C" void kernel_launch(void* const* d_in, const int* in_sizes, int n_in,
                              void* d_out, int out_size)
{
    (void)in_sizes; (void)n_in; (void)out_size;
    const float*  sx   = (const float*)d_in[0];
    const float*  sy   = (const float*)d_in[1];
    const float*  syaw = (const float*)d_in[2];
    const float*  ssp  = (const float*)d_in[3];
    const float4* acc  = (const float4*)d_in[4];
    const float4* str  = (const float4*)d_in[5];

    bicycle_kernel<<<BV / BLK, BLK>>>(sx, sy, syaw, ssp, acc, str, (float4*)d_out);
}

// round 5
// speedup vs baseline: 1.2256x; 1.2256x over previous
#include <cuda_runtime.h>

// BicycleModel: B=65536 vehicles, 256 steps, 4 output planes [B,256] f32.
// R5: TC=32 chunks so every global wavefront is a FULL 128B line.
//  - warp-autonomous: BLK=32, one warp per block, 8 blocks/SM (26.9KB smem)
//  - states staged per-plane float4[v][q], stride 9 -> conflict-free STS/LDS.128
//  - stores: 8 lanes cover one vehicle's full 32-t line -> 4 full-line wf/STG
//  - controls: v-major scalar smem stride 33 (CF compute loads), 16-t half
//    granularity with register prefetch (<=32 regs in flight)

constexpr int BV   = 65536;
constexpr int NS   = 256;
constexpr int BLK  = 32;
constexpr int NCH  = 8;            // chunks of 32 timesteps
constexpr int NF4  = NS / 4;       // 64 float4 per row
constexpr int CSTR = 33;           // ctrl row stride (floats), v-major
constexpr int QSTR = 9;            // state row stride (float4)

constexpr float DT        = 0.05f;
constexpr float MAX_STEER = 0.52359877559829887f;
constexpr float MAX_SPEED = 100.0f;
constexpr float INV_WB    = 1.0f / 2.7f;

__global__ __launch_bounds__(BLK)
void bicycle_kernel(const float*  __restrict__ sx,
                    const float*  __restrict__ sy,
                    const float*  __restrict__ syaw,
                    const float*  __restrict__ ssp,
                    const float4* __restrict__ acc,
                    const float4* __restrict__ str,
                    float4*       __restrict__ out)
{
    __shared__ float  ca[32 * CSTR];           // acc,   ca[v*33 + t_local]
    __shared__ float  cs[32 * CSTR];           // steer
    __shared__ float4 st[4][32 * QSTR];        // planes x,y,yaw,sp: [v*9 + q]

    const int lane = threadIdx.x;
    const int vb   = blockIdx.x * BLK;
    const int b    = vb + lane;

    float x   = sx[b];
    float y   = sy[b];
    float yaw = syaw[b];
    float sp  = ssp[b];

    const unsigned plane4 = (unsigned)BV * NF4;
    const float4* arow = acc + (unsigned)vb * NF4;
    const float4* srow = str + (unsigned)vb * NF4;
    float4*       orow = out + (unsigned)vb * NF4;

    const float* pa = ca + lane * CSTR;
    const float* ps = cs + lane * CSTR;

    float4 ra[4], rs[4];

    // Load one 16-t half of chunk c into registers (coalesced 64B segments).
#define LOADH(c, h)                                                          \
    _Pragma("unroll")                                                        \
    for (int it = 0; it < 4; ++it) {                                         \
        int f4 = it * 32 + lane;                                             \
        int v = f4 >> 2, t4 = f4 & 3;                                        \
        unsigned g = (unsigned)v * NF4 + (unsigned)(c) * 8 + (h) * 4 + t4;   \
        ra[it] = arow[g];                                                    \
        rs[it] = srow[g];                                                    \
    }

    // Scatter registers into v-major ctrl smem rows [h*16 .. h*16+15].
#define STAGEH(h)                                                            \
    _Pragma("unroll")                                                        \
    for (int it = 0; it < 4; ++it) {                                         \
        int f4 = it * 32 + lane;                                             \
        int v = f4 >> 2, t4 = f4 & 3;                                        \
        int o = v * CSTR + (h) * 16 + t4 * 4;                                \
        ca[o] = ra[it].x; ca[o+1] = ra[it].y; ca[o+2] = ra[it].z; ca[o+3] = ra[it].w; \
        cs[o] = rs[it].x; cs[o+1] = rs[it].y; cs[o+2] = rs[it].z; cs[o+3] = rs[it].w; \
    }

#define STEP(A, ST) do {                                                     \
        float fr   = fmaf(0.01f * sp, sp, 0.1f * sp);                        \
        float spn  = fminf(fmaxf(fmaf(DT, (A) - fr, sp), 0.0f), MAX_SPEED);  \
        float sc   = fminf(fmaxf((ST), -MAX_STEER), MAX_STEER);              \
        float angv = sp * __tanf(sc) * INV_WB;                               \
        float sn, cc;                                                        \
        __sincosf(yaw, &sn, &cc);                                            \
        x   = fmaf(sp * cc, DT, x);                                          \
        y   = fmaf(sp * sn, DT, y);                                          \
        yaw = fmaf(angv, DT, yaw);                                           \
        sp  = spn;                                                           \
    } while (0)

    // Prologue: stage both halves of chunk 0.
    LOADH(0, 0); STAGEH(0);
    LOADH(0, 1); STAGEH(1);
    __syncwarp();

    for (int c = 0; c < NCH; ++c) {
        if (c + 1 < NCH) { LOADH(c + 1, 0); }   // prefetch next halfA

        float4 X, Y, W, S;

        // steps 0..15 (local t), buffering pre-step state per 4 steps
#pragma unroll
        for (int q = 0; q < 4; ++q) {
            const float* a4 = pa + q * 4;
            const float* s4 = ps + q * 4;
            X.x = x; Y.x = y; W.x = yaw; S.x = sp;  STEP(a4[0], s4[0]);
            X.y = x; Y.y = y; W.y = yaw; S.y = sp;  STEP(a4[1], s4[1]);
            X.z = x; Y.z = y; W.z = yaw; S.z = sp;  STEP(a4[2], s4[2]);
            X.w = x; Y.w = y; W.w = yaw; S.w = sp;
            int o = lane * QSTR + q;
            st[0][o] = X; st[1][o] = Y; st[2][o] = W; st[3][o] = S;
            STEP(a4[3], s4[3]);
        }
        __syncwarp();

        if (c + 1 < NCH) { STAGEH(0); LOADH(c + 1, 1); }  // stage halfA, prefetch halfB

        // steps 16..31
#pragma unroll
        for (int q = 4; q < 8; ++q) {
            const float* a4 = pa + q * 4;
            const float* s4 = ps + q * 4;
            X.x = x; Y.x = y; W.x = yaw; S.x = sp;  STEP(a4[0], s4[0]);
            X.y = x; Y.y = y; W.y = yaw; S.y = sp;  STEP(a4[1], s4[1]);
            X.z = x; Y.z = y; W.z = yaw; S.z = sp;  STEP(a4[2], s4[2]);
            X.w = x; Y.w = y; W.w = yaw; S.w = sp;
            int o = lane * QSTR + q;
            st[0][o] = X; st[1][o] = Y; st[2][o] = W; st[3][o] = S;
            STEP(a4[3], s4[3]);
        }
        __syncwarp();

        // Store phase: full-line STG.128 (8 lanes cover one vehicle's 128B strip).
#pragma unroll
        for (int it = 0; it < 8; ++it) {
            int v = it * 4 + (lane >> 3);
            int q = lane & 7;
            int o = v * QSTR + q;
            unsigned g = (unsigned)v * NF4 + (unsigned)c * 8 + q;
            orow[g]               = st[0][o];
            orow[plane4 + g]      = st[1][o];
            orow[2 * plane4 + g]  = st[2][o];
            orow[3 * plane4 + g]  = st[3][o];
        }
        if (c + 1 < NCH) { STAGEH(1); }          // stage halfB for next chunk
        __syncwarp();
    }
#undef STEP
#undef STAGEH
#undef LOADH
}

extern "C" void kernel_launch(void* const* d_in, const int* in_sizes, int n_in,
                              void* d_out, int out_size)
{
    (void)in_sizes; (void)n_in; (void)out_size;
    const float*  sx   = (const float*)d_in[0];
    const float*  sy   = (const float*)d_in[1];
    const float*  syaw = (const float*)d_in[2];
    const float*  ssp  = (const float*)d_in[3];
    const float4* acc  = (const float4*)d_in[4];
    const float4* str  = (const float4*)d_in[5];

    bicycle_kernel<<<BV / BLK, BLK>>>(sx, sy, syaw, ssp, acc, str, (float4*)d_out);
}